// round 1
// baseline (speedup 1.0000x reference)
#include <cuda_runtime.h>

// SoftCountPixels: Y[b,p] = (1/(H*W)) * sum_{h,w} exp(-||x[b,:,h,w] - P[p,:]||_2 / (2*0.3))
// x: (16, 3, 256, 256) f32 planar (channel stride = H*W)
// P: (32, 3) f32
// out: (16, 32) f32

#define B 16
#define CH 3
#define H 256
#define W 256
#define HW (H * W)
#define NPRO 32
#define THREADS 256
#define CHUNKS 32   // blocks per batch

// exp(-r / (2*0.3)) = ex2(-(log2 e / 0.6) * r)
#define NEG_K (-2.4044917348149837f)  // -log2(e)/0.6

__device__ __forceinline__ float fast_sqrt(float x) {
    float r;
    asm("sqrt.approx.f32 %0, %1;" : "=f"(r) : "f"(x));
    return r;
}
__device__ __forceinline__ float fast_ex2(float x) {
    float r;
    asm("ex2.approx.f32 %0, %1;" : "=f"(r) : "f"(x));
    return r;
}

__global__ void zero_out_kernel(float* out, int n) {
    int i = blockIdx.x * blockDim.x + threadIdx.x;
    if (i < n) out[i] = 0.0f;
}

__global__ __launch_bounds__(THREADS)
void softcount_kernel(const float* __restrict__ x,
                      const float* __restrict__ P,
                      float* __restrict__ out) {
    __shared__ float q0[NPRO], q1[NPRO], q2[NPRO], cc[NPRO];
    __shared__ float sacc[NPRO];

    const int tid = threadIdx.x;
    const int b   = blockIdx.y;

    if (tid < NPRO) {
        float p0 = P[tid * 3 + 0];
        float p1 = P[tid * 3 + 1];
        float p2 = P[tid * 3 + 2];
        q0[tid] = -2.0f * p0;
        q1[tid] = -2.0f * p1;
        q2[tid] = -2.0f * p2;
        cc[tid] = p0 * p0 + p1 * p1 + p2 * p2;  // ||P||^2
        sacc[tid] = 0.0f;
    }
    __syncthreads();

    float acc[NPRO];
#pragma unroll
    for (int p = 0; p < NPRO; p++) acc[p] = 0.0f;

    const float* xb = x + (size_t)b * CH * HW;

    for (int pix = blockIdx.x * THREADS + tid; pix < HW; pix += CHUNKS * THREADS) {
        const float x0 = xb[pix];
        const float x1 = xb[pix + HW];
        const float x2 = xb[pix + 2 * HW];
        const float xx = x0 * x0 + x1 * x1 + x2 * x2;  // ||x||^2

#pragma unroll
        for (int p = 0; p < NPRO; p++) {
            float t = cc[p] + xx;                // ||P||^2 + ||x||^2
            t = fmaf(q0[p], x0, t);              // -2 P.x
            t = fmaf(q1[p], x1, t);
            t = fmaf(q2[p], x2, t);
            t = fmaxf(t, 0.0f);                  // guard cancellation
            float r = fast_sqrt(t);              // MUFU.SQRT
            acc[p] += fast_ex2(NEG_K * r);       // FMUL + MUFU.EX2
        }
    }

    // warp reduce each of the 32 accumulators, lane 0 adds into shared
    const int lane = tid & 31;
#pragma unroll
    for (int p = 0; p < NPRO; p++) {
        float v = acc[p];
#pragma unroll
        for (int off = 16; off > 0; off >>= 1)
            v += __shfl_xor_sync(0xFFFFFFFFu, v, off);
        if (lane == 0) atomicAdd(&sacc[p], v);
    }
    __syncthreads();

    if (tid < NPRO) {
        // 1/(H*W) is a power of two -> exact scale
        atomicAdd(&out[b * NPRO + tid], sacc[tid] * (1.0f / (float)HW));
    }
}

extern "C" void kernel_launch(void* const* d_in, const int* in_sizes, int n_in,
                              void* d_out, int out_size) {
    const float* x = (const float*)d_in[0];
    const float* P = (const float*)d_in[1];
    float* out = (float*)d_out;

    zero_out_kernel<<<(out_size + 255) / 256, 256>>>(out, out_size);

    dim3 grid(CHUNKS, B);
    softcount_kernel<<<grid, THREADS>>>(x, P, out);
}

// round 2
// speedup vs baseline: 1.7328x; 1.7328x over previous
#include <cuda_runtime.h>

// SoftCountPixels: Y[b,p] = (1/(H*W)) * sum_{h,w} exp(-||x[b,:,h,w] - P[p,:]||_2 / 0.6)
// x: (16, 3, 256, 256) f32 planar; P: (32, 3) f32; out: (16, 32) f32
//
// Trick: exp(-d/0.6) = ex2(-(log2e/0.6)*d) = ex2(-sqrt(K2*d^2)), K2=(log2e/0.6)^2.
// Pre-scaling the quadratic form by K2 removes the FMUL before EX2; the FNEG
// folds into the MUFU.EX2 source modifier. Inner loop = 8 issues/pair,
// 2 of which are MUFU -> MUFU pipe (rt_SMSP=8) is the binding pipe.

#define B 16
#define HW (256 * 256)
#define HW4 (HW / 4)
#define NPRO 32
#define PPT 8        // protos per thread (proto-group)
#define PGROUPS (NPRO / PPT)
#define THREADS 256
#define CHUNKS 6     // blocks per (batch, proto-group): 6*16*4 = 384 = 1 wave @ 3 CTA/SM

#define K2 5.781580510735007f  // (log2(e)/0.6)^2

__device__ __forceinline__ float fast_sqrt(float v) {
    float r;
    asm("sqrt.approx.f32 %0, %1;" : "=f"(r) : "f"(v));
    return r;
}
__device__ __forceinline__ float fast_ex2(float v) {
    float r;
    asm("ex2.approx.f32 %0, %1;" : "=f"(r) : "f"(v));
    return r;
}

__global__ void zero_out_kernel(float* out, int n) {
    int i = blockIdx.x * blockDim.x + threadIdx.x;
    if (i < n) out[i] = 0.0f;
}

__global__ __launch_bounds__(THREADS, 3)
void softcount_kernel(const float* __restrict__ x,
                      const float* __restrict__ P,
                      float* __restrict__ out) {
    __shared__ float sacc[PPT];

    const int tid = threadIdx.x;
    const int b   = blockIdx.y;
    const int pg  = blockIdx.z;

    // Per-thread proto constants, pre-scaled by K2.
    float qk0[PPT], qk1[PPT], qk2[PPT], cck[PPT], acc[PPT];
#pragma unroll
    for (int i = 0; i < PPT; i++) {
        const int p = pg * PPT + i;
        const float p0 = P[p * 3 + 0];
        const float p1 = P[p * 3 + 1];
        const float p2 = P[p * 3 + 2];
        qk0[i] = -2.0f * K2 * p0;
        qk1[i] = -2.0f * K2 * p1;
        qk2[i] = -2.0f * K2 * p2;
        cck[i] = K2 * (p0 * p0 + p1 * p1 + p2 * p2);
        acc[i] = 0.0f;
    }
    if (tid < PPT) sacc[tid] = 0.0f;
    __syncthreads();

    const float4* x0p = (const float4*)(x + (size_t)b * 3 * HW);
    const float4* x1p = x0p + HW4;
    const float4* x2p = x1p + HW4;

    for (int i4 = blockIdx.x * THREADS + tid; i4 < HW4; i4 += CHUNKS * THREADS) {
        const float4 v0 = x0p[i4];
        const float4 v1 = x1p[i4];
        const float4 v2 = x2p[i4];

        const float px0[4] = {v0.x, v0.y, v0.z, v0.w};
        const float px1[4] = {v1.x, v1.y, v1.z, v1.w};
        const float px2[4] = {v2.x, v2.y, v2.z, v2.w};

#pragma unroll
        for (int j = 0; j < 4; j++) {
            const float x0 = px0[j];
            const float x1 = px1[j];
            const float x2 = px2[j];
            float xx = x0 * x0;
            xx = fmaf(x1, x1, xx);
            xx = fmaf(x2, x2, xx);
            const float xxk = K2 * xx;

#pragma unroll
            for (int i = 0; i < PPT; i++) {
                float t = cck[i] + xxk;
                t = fmaf(qk0[i], x0, t);
                t = fmaf(qk1[i], x1, t);
                t = fmaf(qk2[i], x2, t);
                t = fmaxf(t, 0.0f);          // guard cancellation
                const float r = fast_sqrt(t); // MUFU.SQRT
                acc[i] += fast_ex2(-r);       // MUFU.EX2 (neg folds into src mod)
            }
        }
    }

    // Reduce 8 accumulators: warp shuffle, then shared atomics, then 1 global atomic.
    const int lane = tid & 31;
#pragma unroll
    for (int i = 0; i < PPT; i++) {
        float v = acc[i];
#pragma unroll
        for (int off = 16; off > 0; off >>= 1)
            v += __shfl_xor_sync(0xFFFFFFFFu, v, off);
        if (lane == 0) atomicAdd(&sacc[i], v);
    }
    __syncthreads();

    if (tid < PPT) {
        atomicAdd(&out[b * NPRO + pg * PPT + tid], sacc[tid] * (1.0f / (float)HW));
    }
}

extern "C" void kernel_launch(void* const* d_in, const int* in_sizes, int n_in,
                              void* d_out, int out_size) {
    const float* x = (const float*)d_in[0];
    const float* P = (const float*)d_in[1];
    float* out = (float*)d_out;

    zero_out_kernel<<<(out_size + 255) / 256, 256>>>(out, out_size);

    dim3 grid(CHUNKS, B, PGROUPS);
    softcount_kernel<<<grid, THREADS>>>(x, P, out);
}

// round 3
// speedup vs baseline: 1.7512x; 1.0106x over previous
#include <cuda_runtime.h>

// SoftCountPixels: Y[b,p] = (1/(H*W)) * sum_{h,w} exp(-||x[b,:,h,w] - P[p,:]||_2 / 0.6)
// x: (16, 3, 256, 256) f32 planar; P: (32, 3) f32; out: (16, 32) f32
//
// exp(-d/0.6) = ex2(-sqrt(K2*d^2)), K2=(log2e/0.6)^2, so the FMUL before EX2
// vanishes (pre-scaled quadratic form) and FNEG folds into the MUFU operand.
// sqrt(|t|) instead of sqrt(max(t,0)): |.| folds into MUFU.SQRT's source
// modifier; the cancellation case (t<0 possible only when d~0) gives exp(-~0)=1,
// which is the correct value.

#define B 16
#define HW (256 * 256)
#define HW4 (HW / 4)
#define NPRO 32
#define PPT 4                    // protos per thread
#define PGROUPS (NPRO / PPT)     // 8
#define THREADS 256
#define CHUNKS 4                 // 16 * 8 * 4 = 512 blocks <= 592 slots @ 4 CTA/SM -> 1 wave

#define K2 5.781580510735007f    // (log2(e)/0.6)^2

__device__ __forceinline__ float fast_sqrt(float v) {
    float r;
    asm("sqrt.approx.f32 %0, %1;" : "=f"(r) : "f"(v));
    return r;
}
__device__ __forceinline__ float fast_ex2(float v) {
    float r;
    asm("ex2.approx.f32 %0, %1;" : "=f"(r) : "f"(v));
    return r;
}

__global__ void zero_out_kernel(float* out, int n) {
    int i = blockIdx.x * blockDim.x + threadIdx.x;
    if (i < n) out[i] = 0.0f;
}

__device__ __forceinline__ float pair_term(float cck, float xxk,
                                           float qk0, float qk1, float qk2,
                                           float x0, float x1, float x2) {
    float t = cck + xxk;
    t = fmaf(qk0, x0, t);
    t = fmaf(qk1, x1, t);
    t = fmaf(qk2, x2, t);
    float r = fast_sqrt(fabsf(t));   // MUFU.SQRT with |.| modifier
    return fast_ex2(-r);             // MUFU.EX2 with neg modifier
}

__global__ __launch_bounds__(THREADS, 4)
void softcount_kernel(const float* __restrict__ x,
                      const float* __restrict__ P,
                      float* __restrict__ out) {
    __shared__ float sacc[PPT];

    const int tid = threadIdx.x;
    const int b   = blockIdx.y;
    const int pg  = blockIdx.z;

    float qk0[PPT], qk1[PPT], qk2[PPT], cck[PPT];
    float acc[PPT];
#pragma unroll
    for (int i = 0; i < PPT; i++) {
        const int p = pg * PPT + i;
        const float p0 = P[p * 3 + 0];
        const float p1 = P[p * 3 + 1];
        const float p2 = P[p * 3 + 2];
        qk0[i] = -2.0f * K2 * p0;
        qk1[i] = -2.0f * K2 * p1;
        qk2[i] = -2.0f * K2 * p2;
        cck[i] = K2 * (p0 * p0 + p1 * p1 + p2 * p2);
        acc[i] = 0.0f;
    }
    if (tid < PPT) sacc[tid] = 0.0f;
    __syncthreads();

    const float4* xb = (const float4*)(x + (size_t)b * 3 * HW);

    for (int i4 = blockIdx.x * THREADS + tid; i4 < HW4; i4 += CHUNKS * THREADS) {
        const float4 v0 = xb[i4];            // channel 0
        const float4 v1 = xb[i4 + HW4];      // channel 1
        const float4 v2 = xb[i4 + 2 * HW4];  // channel 2

        // pixel 0
        {
            float xx = v0.x * v0.x; xx = fmaf(v1.x, v1.x, xx); xx = fmaf(v2.x, v2.x, xx);
            const float xxk = K2 * xx;
#pragma unroll
            for (int i = 0; i < PPT; i++)
                acc[i] += pair_term(cck[i], xxk, qk0[i], qk1[i], qk2[i], v0.x, v1.x, v2.x);
        }
        // pixel 1
        {
            float xx = v0.y * v0.y; xx = fmaf(v1.y, v1.y, xx); xx = fmaf(v2.y, v2.y, xx);
            const float xxk = K2 * xx;
#pragma unroll
            for (int i = 0; i < PPT; i++)
                acc[i] += pair_term(cck[i], xxk, qk0[i], qk1[i], qk2[i], v0.y, v1.y, v2.y);
        }
        // pixel 2
        {
            float xx = v0.z * v0.z; xx = fmaf(v1.z, v1.z, xx); xx = fmaf(v2.z, v2.z, xx);
            const float xxk = K2 * xx;
#pragma unroll
            for (int i = 0; i < PPT; i++)
                acc[i] += pair_term(cck[i], xxk, qk0[i], qk1[i], qk2[i], v0.z, v1.z, v2.z);
        }
        // pixel 3
        {
            float xx = v0.w * v0.w; xx = fmaf(v1.w, v1.w, xx); xx = fmaf(v2.w, v2.w, xx);
            const float xxk = K2 * xx;
#pragma unroll
            for (int i = 0; i < PPT; i++)
                acc[i] += pair_term(cck[i], xxk, qk0[i], qk1[i], qk2[i], v0.w, v1.w, v2.w);
        }
    }

    // Reduce: warp shuffle, shared atomics, one global atomic per (b,p) per block.
    const int lane = tid & 31;
#pragma unroll
    for (int i = 0; i < PPT; i++) {
        float v = acc[i];
#pragma unroll
        for (int off = 16; off > 0; off >>= 1)
            v += __shfl_xor_sync(0xFFFFFFFFu, v, off);
        if (lane == 0) atomicAdd(&sacc[i], v);
    }
    __syncthreads();

    if (tid < PPT) {
        atomicAdd(&out[b * NPRO + pg * PPT + tid], sacc[tid] * (1.0f / (float)HW));
    }
}

extern "C" void kernel_launch(void* const* d_in, const int* in_sizes, int n_in,
                              void* d_out, int out_size) {
    const float* x = (const float*)d_in[0];
    const float* P = (const float*)d_in[1];
    float* out = (float*)d_out;

    zero_out_kernel<<<(out_size + 255) / 256, 256>>>(out, out_size);

    dim3 grid(CHUNKS, B, PGROUPS);
    softcount_kernel<<<grid, THREADS>>>(x, P, out);
}

// round 4
// speedup vs baseline: 1.8774x; 1.0721x over previous
#include <cuda_runtime.h>
#include <cstdint>

// SoftCountPixels: Y[b,p] = (1/(H*W)) * sum_{h,w} exp(-||x[b,:,h,w] - P[p,:]||_2 / 0.6)
// x: (16, 3, 256, 256) f32 planar; P: (32, 3) f32; out: (16, 32) f32
//
// exp(-d/0.6) = ex2(-sqrt(K2*d^2)), K2 = (log2e/0.6)^2: pre-scaled quadratic
// form kills the FMUL before EX2; |.| and neg fold into MUFU source modifiers.
// All pair-side FMA work is done in packed f32x2 (2 pixels per instruction),
// which ptxas can't generate from C++ — inline PTX fma.rn.f32x2/add.rn.f32x2.
// The MUFU pipe (SQRT+EX2, 2 per pair) is then the binding resource.

#define B 16
#define HW (256 * 256)
#define HW4 (HW / 4)
#define NPRO 32
#define PPT 4                    // protos per thread
#define PGROUPS (NPRO / PPT)     // 8
#define THREADS 256
#define CHUNKS 3                 // 3*16*8 = 384 blocks <= 444 slots @ 3 CTA/SM -> 1 wave

#define K2 5.781580510735007f    // (log2(e)/0.6)^2

__device__ __forceinline__ float fast_sqrt(float v) {
    float r;
    asm("sqrt.approx.f32 %0, %1;" : "=f"(r) : "f"(v));
    return r;
}
__device__ __forceinline__ float fast_ex2(float v) {
    float r;
    asm("ex2.approx.f32 %0, %1;" : "=f"(r) : "f"(v));
    return r;
}

// ---- packed f32x2 helpers ----
__device__ __forceinline__ uint64_t pack2(float lo, float hi) {
    uint64_t r;
    asm("mov.b64 %0, {%1, %2};" : "=l"(r) : "f"(lo), "f"(hi));
    return r;
}
__device__ __forceinline__ void unpack2(uint64_t v, float& lo, float& hi) {
    asm("mov.b64 {%0, %1}, %2;" : "=f"(lo), "=f"(hi) : "l"(v));
}
__device__ __forceinline__ uint64_t fma2(uint64_t a, uint64_t b, uint64_t c) {
    uint64_t r;
    asm("fma.rn.f32x2 %0, %1, %2, %3;" : "=l"(r) : "l"(a), "l"(b), "l"(c));
    return r;
}
__device__ __forceinline__ uint64_t add2(uint64_t a, uint64_t b) {
    uint64_t r;
    asm("add.rn.f32x2 %0, %1, %2;" : "=l"(r) : "l"(a), "l"(b));
    return r;
}
__device__ __forceinline__ uint64_t mul2(uint64_t a, uint64_t b) {
    uint64_t r;
    asm("mul.rn.f32x2 %0, %1, %2;" : "=l"(r) : "l"(a), "l"(b));
    return r;
}

__global__ void zero_out_kernel(float* out, int n) {
    int i = blockIdx.x * blockDim.x + threadIdx.x;
    if (i < n) out[i] = 0.0f;
}

__global__ __launch_bounds__(THREADS, 3)
void softcount_kernel(const float* __restrict__ x,
                      const float* __restrict__ P,
                      float* __restrict__ out) {
    __shared__ float sacc[PPT];

    const int tid = threadIdx.x;
    const int b   = blockIdx.y;
    const int pg  = blockIdx.z;

    // Packed (broadcast) per-proto constants, pre-scaled by K2.
    uint64_t qk0[PPT], qk1[PPT], qk2[PPT], cck[PPT];
    float accA[PPT], accB[PPT];
#pragma unroll
    for (int i = 0; i < PPT; i++) {
        const int p = pg * PPT + i;
        const float p0 = P[p * 3 + 0];
        const float p1 = P[p * 3 + 1];
        const float p2 = P[p * 3 + 2];
        const float q0 = -2.0f * K2 * p0;
        const float q1 = -2.0f * K2 * p1;
        const float q2 = -2.0f * K2 * p2;
        const float cc = K2 * (p0 * p0 + p1 * p1 + p2 * p2);
        qk0[i] = pack2(q0, q0);
        qk1[i] = pack2(q1, q1);
        qk2[i] = pack2(q2, q2);
        cck[i] = pack2(cc, cc);
        accA[i] = 0.0f;
        accB[i] = 0.0f;
    }
    const uint64_t K2_2 = pack2(K2, K2);
    if (tid < PPT) sacc[tid] = 0.0f;
    __syncthreads();

    const float4* xb = (const float4*)(x + (size_t)b * 3 * HW);

    for (int i4 = blockIdx.x * THREADS + tid; i4 < HW4; i4 += CHUNKS * THREADS) {
        const float4 v0 = xb[i4];            // channel 0, pixels 0..3
        const float4 v1 = xb[i4 + HW4];      // channel 1
        const float4 v2 = xb[i4 + 2 * HW4];  // channel 2

        // ---- pixel pair (0,1) ----
        {
            const uint64_t X0 = pack2(v0.x, v0.y);
            const uint64_t X1 = pack2(v1.x, v1.y);
            const uint64_t X2 = pack2(v2.x, v2.y);
            uint64_t xx = mul2(X0, X0);
            xx = fma2(X1, X1, xx);
            xx = fma2(X2, X2, xx);
            const uint64_t xxk = mul2(K2_2, xx);
#pragma unroll
            for (int i = 0; i < PPT; i++) {
                uint64_t t = add2(cck[i], xxk);
                t = fma2(qk0[i], X0, t);
                t = fma2(qk1[i], X1, t);
                t = fma2(qk2[i], X2, t);
                float ta, tb;
                unpack2(t, ta, tb);
                accA[i] += fast_ex2(-fast_sqrt(fabsf(ta)));
                accB[i] += fast_ex2(-fast_sqrt(fabsf(tb)));
            }
        }
        // ---- pixel pair (2,3) ----
        {
            const uint64_t X0 = pack2(v0.z, v0.w);
            const uint64_t X1 = pack2(v1.z, v1.w);
            const uint64_t X2 = pack2(v2.z, v2.w);
            uint64_t xx = mul2(X0, X0);
            xx = fma2(X1, X1, xx);
            xx = fma2(X2, X2, xx);
            const uint64_t xxk = mul2(K2_2, xx);
#pragma unroll
            for (int i = 0; i < PPT; i++) {
                uint64_t t = add2(cck[i], xxk);
                t = fma2(qk0[i], X0, t);
                t = fma2(qk1[i], X1, t);
                t = fma2(qk2[i], X2, t);
                float ta, tb;
                unpack2(t, ta, tb);
                accA[i] += fast_ex2(-fast_sqrt(fabsf(ta)));
                accB[i] += fast_ex2(-fast_sqrt(fabsf(tb)));
            }
        }
    }

    // Reduce: warp shuffle, shared atomics, one global atomic per (b,p) per block.
    const int lane = tid & 31;
#pragma unroll
    for (int i = 0; i < PPT; i++) {
        float v = accA[i] + accB[i];
#pragma unroll
        for (int off = 16; off > 0; off >>= 1)
            v += __shfl_xor_sync(0xFFFFFFFFu, v, off);
        if (lane == 0) atomicAdd(&sacc[i], v);
    }
    __syncthreads();

    if (tid < PPT) {
        atomicAdd(&out[b * NPRO + pg * PPT + tid], sacc[tid] * (1.0f / (float)HW));
    }
}

extern "C" void kernel_launch(void* const* d_in, const int* in_sizes, int n_in,
                              void* d_out, int out_size) {
    const float* x = (const float*)d_in[0];
    const float* P = (const float*)d_in[1];
    float* out = (float*)d_out;

    zero_out_kernel<<<(out_size + 255) / 256, 256>>>(out, out_size);

    dim3 grid(CHUNKS, B, PGROUPS);
    softcount_kernel<<<grid, THREADS>>>(x, P, out);
}